// round 7
// baseline (speedup 1.0000x reference)
#include <cuda_runtime.h>
#include <cstdint>

// ---------------- static scratch (device globals: allocation-free) ----------------
#define NMAX 100000
#define EMAX 1600000
#define HDIM 64

__device__ float g_deg[NMAX];
__device__ float g_dis[NMAX];
__device__ float g_wn[EMAX];
__device__ int   g_src[EMAX];
__device__ int   g_tgt[EMAX];
__device__ float g_bufA[(size_t)NMAX * HDIM];
__device__ float g_bufB[(size_t)NMAX * HDIM];
__device__ float g_tx1[(size_t)NMAX * HDIM];
__device__ float g_tmp[(size_t)NMAX * HDIM];
__device__ float g_weff[4 * 192 * 64];
__device__ float g_sums[64];
__device__ float g_cnt[64];

// ---------------- utility ----------------
__global__ void zero4_kernel(float* __restrict__ p, int n4) {
    int i = blockIdx.x * blockDim.x + threadIdx.x;
    if (i < n4) reinterpret_cast<float4*>(p)[i] = make_float4(0.f, 0.f, 0.f, 0.f);
}

__global__ void zero_pool_kernel() {
    int i = threadIdx.x;
    if (i < 64) g_sums[i] = 0.f;
    else if (i < 128) g_cnt[i - 64] = 0.f;
}

// ---------------- preprocessing ----------------
// edge_index is int32 (JAX default x64-disabled downcasts the reference's int64).
__global__ void edge_prep_kernel(const int* __restrict__ ei,
                                 const float* __restrict__ ew, int E, int N) {
    int e = blockIdx.x * blockDim.x + threadIdx.x;
    if (e >= E) return;
    int s = ei[e];
    int t = ei[(size_t)E + e];
    // bounds-harden: clamp garbage into range instead of crashing
    if ((unsigned)s >= (unsigned)N) s = 0;
    if ((unsigned)t >= (unsigned)N) t = 0;
    g_src[e] = s;
    g_tgt[e] = t;
    atomicAdd(&g_deg[s], ew[e]);
}

__global__ void dis_kernel(int n) {
    int i = blockIdx.x * blockDim.x + threadIdx.x;
    if (i >= n) return;
    float d = g_deg[i];
    g_dis[i] = (d > 0.f) ? rsqrtf(d) : 0.f;
}

__global__ void wn_kernel(const float* __restrict__ ew, int E) {
    int e = blockIdx.x * blockDim.x + threadIdx.x;
    if (e >= E) return;
    g_wn[e] = -g_dis[g_src[e]] * ew[e] * g_dis[g_tgt[e]];
}

// Weff[l][kk][o]: kk<64 -> W0-W2 ; 64..127 -> W1 ; 128..191 -> 2*W2
__global__ void weff_kernel(const float* __restrict__ w) {
    int idx = blockIdx.x * blockDim.x + threadIdx.x;
    if (idx >= 4 * 192 * 64) return;
    int o  = idx & 63;
    int kk = (idx >> 6) % 192;
    int l  = idx / (192 * 64);
    const float* wl = w + (size_t)l * 3 * 4096;
    float v;
    if (kk < 64)       v = wl[kk * 64 + o] - wl[2 * 4096 + kk * 64 + o];
    else if (kk < 128) v = wl[4096 + (kk - 64) * 64 + o];
    else               v = 2.f * wl[2 * 4096 + (kk - 128) * 64 + o];
    g_weff[idx] = v;
}

// ---------------- sparse propagation: out[tgt] += wn * h[src] ----------------
// 16 lanes per edge, float4 per lane, vector red to L2.
__global__ void prop_kernel(const float* __restrict__ h, float* __restrict__ out, int E) {
    int gid = blockIdx.x * blockDim.x + threadIdx.x;
    int e = gid >> 4;
    if (e >= E) return;
    int l = (gid & 15) << 2;
    int s = g_src[e];
    int t = g_tgt[e];
    float w = g_wn[e];
    float4 v = *reinterpret_cast<const float4*>(h + (size_t)s * HDIM + l);
    v.x *= w; v.y *= w; v.z *= w; v.w *= w;
    float* dst = out + (size_t)t * HDIM + l;
    asm volatile("red.global.add.v4.f32 [%0], {%1, %2, %3, %4};"
                 :: "l"(dst), "f"(v.x), "f"(v.y), "f"(v.z), "f"(v.w)
                 : "memory");
}

// ---------------- fused layer GEMM: out = [p0|p1|p2] @ Weff + bias ----------------
// M-tile 64 nodes, N=64 outs, K=192. 256 threads, each computes 4x4.
__global__ void gemm_kernel(const float* __restrict__ p0, const float* __restrict__ p1,
                            const float* __restrict__ p2, const float* __restrict__ Weff,
                            const float* __restrict__ bias, float* __restrict__ out,
                            int n_nodes) {
    __shared__ float As[16][64];
    __shared__ float Bs[16][64];
    __shared__ float bsm[64];
    int tid = threadIdx.x;
    int m0 = blockIdx.x * 64;
    if (tid < 64) bsm[tid] = bias[tid];
    int ty = tid >> 4;        // 0..15 -> node group
    int tx = tid & 15;        // 0..15 -> out group
    float c[4][4];
#pragma unroll
    for (int i = 0; i < 4; i++)
#pragma unroll
        for (int j = 0; j < 4; j++) c[i][j] = 0.f;

    const float* parts[3] = {p0, p1, p2};

#pragma unroll 1
    for (int kt = 0; kt < 12; kt++) {
        int kg = kt * 16;
        const float* P = parts[kg >> 6];
        int ko = kg & 63;
        // load A tile (64 nodes x 16 k), store transposed
        {
            int node_l = tid >> 2;
            int k4 = (tid & 3) << 2;
            float4 av = make_float4(0.f, 0.f, 0.f, 0.f);
            int node = m0 + node_l;
            if (node < n_nodes)
                av = *reinterpret_cast<const float4*>(P + (size_t)node * 64 + ko + k4);
            As[k4 + 0][node_l] = av.x;
            As[k4 + 1][node_l] = av.y;
            As[k4 + 2][node_l] = av.z;
            As[k4 + 3][node_l] = av.w;
        }
        // load B tile (16 k x 64 outs)
        {
            int kr = tid >> 4;
            int c4 = (tid & 15) << 2;
            float4 bv = *reinterpret_cast<const float4*>(Weff + (size_t)(kg + kr) * 64 + c4);
            *reinterpret_cast<float4*>(&Bs[kr][c4]) = bv;
        }
        __syncthreads();
#pragma unroll
        for (int k = 0; k < 16; k++) {
            float4 a = *reinterpret_cast<const float4*>(&As[k][ty << 2]);
            float4 b = *reinterpret_cast<const float4*>(&Bs[k][tx << 2]);
            c[0][0] += a.x * b.x; c[0][1] += a.x * b.y; c[0][2] += a.x * b.z; c[0][3] += a.x * b.w;
            c[1][0] += a.y * b.x; c[1][1] += a.y * b.y; c[1][2] += a.y * b.z; c[1][3] += a.y * b.w;
            c[2][0] += a.z * b.x; c[2][1] += a.z * b.y; c[2][2] += a.z * b.z; c[2][3] += a.z * b.w;
            c[3][0] += a.w * b.x; c[3][1] += a.w * b.y; c[3][2] += a.w * b.z; c[3][3] += a.w * b.w;
        }
        __syncthreads();
    }
    // epilogue: add bias, store
#pragma unroll
    for (int i = 0; i < 4; i++) {
        int node = m0 + (ty << 2) + i;
        if (node < n_nodes) {
            float4 o;
            int n0 = tx << 2;
            o.x = c[i][0] + bsm[n0 + 0];
            o.y = c[i][1] + bsm[n0 + 1];
            o.z = c[i][2] + bsm[n0 + 2];
            o.w = c[i][3] + bsm[n0 + 3];
            *reinterpret_cast<float4*>(out + (size_t)node * 64 + n0) = o;
        }
    }
}

// ---------------- readout MLP (64->32 relu ->1) + scatter mean ----------------
__global__ void readout_kernel(const float* __restrict__ y, const int* __restrict__ batch,
                               const float* __restrict__ wr1, const float* __restrict__ br1,
                               const float* __restrict__ wr2, const float* __restrict__ br2,
                               int n, int G) {
    __shared__ float Wsm[64 * 32];
    __shared__ float w2sm[32];
    __shared__ float b1sm[32];
    for (int i = threadIdx.x; i < 64 * 32; i += blockDim.x) Wsm[i] = wr1[i];
    if (threadIdx.x < 32) {
        w2sm[threadIdx.x] = wr2[threadIdx.x];
        b1sm[threadIdx.x] = br1[threadIdx.x];
    }
    __syncthreads();
    float b2 = br2[0];
    int lane = threadIdx.x & 31;
    int warp = (blockIdx.x * blockDim.x + threadIdx.x) >> 5;
    int nwarps = (gridDim.x * blockDim.x) >> 5;
    for (int node = warp; node < n; node += nwarps) {
        float yv0 = y[(size_t)node * 64 + lane];
        float yv1 = y[(size_t)node * 64 + 32 + lane];
        float acc = b1sm[lane];
#pragma unroll
        for (int k = 0; k < 32; k++)
            acc += __shfl_sync(0xffffffffu, yv0, k) * Wsm[k * 32 + lane];
#pragma unroll
        for (int k = 0; k < 32; k++)
            acc += __shfl_sync(0xffffffffu, yv1, k) * Wsm[(32 + k) * 32 + lane];
        acc = fmaxf(acc, 0.f);
        float r = acc * w2sm[lane];
#pragma unroll
        for (int off = 16; off; off >>= 1)
            r += __shfl_xor_sync(0xffffffffu, r, off);
        if (lane == 0) {
            int g = batch[node];
            if ((unsigned)g < (unsigned)G) {
                atomicAdd(&g_sums[g], r + b2);
                atomicAdd(&g_cnt[g], 1.f);
            }
        }
    }
}

__global__ void finalize_kernel(float* __restrict__ out, int G) {
    int g = threadIdx.x;
    if (g < G) out[g] = g_sums[g] / fmaxf(g_cnt[g], 1.f);
}

// ---------------- host ----------------
extern "C" void kernel_launch(void* const* d_in, const int* in_sizes, int n_in,
                              void* d_out, int out_size) {
    const float* x        = (const float*)d_in[0];
    const int*   ei       = (const int*)d_in[1];     // int32 (JAX x64 disabled)
    const float* ew       = (const float*)d_in[2];
    const int*   batch    = (const int*)d_in[3];     // int32
    const float* w_layers = (const float*)d_in[4];
    const float* b_layers = (const float*)d_in[5];
    const float* wr1      = (const float*)d_in[6];
    const float* br1      = (const float*)d_in[7];
    const float* wr2      = (const float*)d_in[8];
    const float* br2      = (const float*)d_in[9];

    int N = in_sizes[0] / HDIM;
    int E = in_sizes[1] / 2;
    int G = out_size;

    float *bufA, *bufB, *tx1, *tmp, *deg, *weff;
    cudaGetSymbolAddress((void**)&bufA, g_bufA);
    cudaGetSymbolAddress((void**)&bufB, g_bufB);
    cudaGetSymbolAddress((void**)&tx1,  g_tx1);
    cudaGetSymbolAddress((void**)&tmp,  g_tmp);
    cudaGetSymbolAddress((void**)&deg,  g_deg);
    cudaGetSymbolAddress((void**)&weff, g_weff);

    const int TPB = 256;

    // preprocessing
    zero4_kernel<<<(N / 4 + TPB - 1) / TPB, TPB>>>(deg, N / 4);
    edge_prep_kernel<<<(E + TPB - 1) / TPB, TPB>>>(ei, ew, E, N);
    dis_kernel<<<(N + TPB - 1) / TPB, TPB>>>(N);
    wn_kernel<<<(E + TPB - 1) / TPB, TPB>>>(ew, E);
    weff_kernel<<<(4 * 192 * 64 + TPB - 1) / TPB, TPB>>>(w_layers);

    int nfeat4 = (N * HDIM) / 4;
    int zgrid = (nfeat4 + TPB - 1) / TPB;
    long long ethreads = (long long)E * 16;
    int pgrid = (int)((ethreads + TPB - 1) / TPB);
    int ggrid = (N + 63) / 64;

    const float* ycur = x;
    float* bufs[2] = {bufA, bufB};
    for (int l = 0; l < 4; l++) {
        zero4_kernel<<<zgrid, TPB>>>(tx1, nfeat4);
        prop_kernel<<<pgrid, TPB>>>(ycur, tx1, E);
        zero4_kernel<<<zgrid, TPB>>>(tmp, nfeat4);
        prop_kernel<<<pgrid, TPB>>>(tx1, tmp, E);
        gemm_kernel<<<ggrid, TPB>>>(ycur, tx1, tmp,
                                    weff + (size_t)l * 192 * 64,
                                    b_layers + (size_t)l * 64,
                                    bufs[l & 1], N);
        ycur = bufs[l & 1];
    }

    // readout + pooling
    zero_pool_kernel<<<1, 128>>>();
    readout_kernel<<<256, TPB>>>(ycur, batch, wr1, br1, wr2, br2, N, G);
    finalize_kernel<<<1, 64>>>((float*)d_out, G);
}